// round 8
// baseline (speedup 1.0000x reference)
#include <cuda_runtime.h>
#include <cuda_bf16.h>
#include <cstdint>

// Problem dims
#define BSZ 16
#define NV  128
#define NT  64
#define DM  512
#define HEADS 8
#define HD  64
#define TOPKN 16
#define BATT (BSZ*NT)          // 1024
#define FULLMASK 0xffffffffu

#define HN ((size_t)BSZ*NV*NT*DM)   // 67,108,864 elements
#define QKN ((size_t)BATT*HEADS*NV*HD)

// ---------- scratch (device globals; no allocation allowed) ----------
__device__ __nv_bfloat16 g_Qhi[QKN];    // [B][H][V][hd], pre-scaled by 1/8
__device__ __nv_bfloat16 g_Qlo[QKN];
__device__ __nv_bfloat16 g_Khi[QKN];
__device__ __nv_bfloat16 g_Klo[QKN];
__device__ float g_V[QKN];              // [B][H][V][hd] fp32
__device__ __nv_bfloat16 g_Hhi[HN];     // h split hi  [m][k], m=(b*128+v)*64+t
__device__ __nv_bfloat16 g_Hlo[HN];
__device__ __nv_bfloat16 g_Mhi[HN];     // mixed split hi [m][k], m=(b*64+t)*128+v
__device__ __nv_bfloat16 g_Mlo[HN];
__device__ __nv_bfloat16 g_Whi[4*DM*DM];  // Wq,Wk,Wv,Wo split hi [n][k]
__device__ __nv_bfloat16 g_Wlo[4*DM*DM];

// ---------- packed f32x2 helpers ----------
__device__ __forceinline__ unsigned long long pack2(float lo, float hi) {
    unsigned long long r;
    asm("mov.b64 %0, {%1, %2};" : "=l"(r) : "f"(lo), "f"(hi));
    return r;
}
__device__ __forceinline__ float2 unpack2(unsigned long long v) {
    float2 r;
    asm("mov.b64 {%0, %1}, %2;" : "=f"(r.x), "=f"(r.y) : "l"(v));
    return r;
}
__device__ __forceinline__ unsigned long long fma2(unsigned long long a,
                                                   unsigned long long b,
                                                   unsigned long long c) {
    unsigned long long d;
    asm("fma.rn.f32x2 %0, %1, %2, %3;" : "=l"(d) : "l"(a), "l"(b), "l"(c));
    return d;
}

// ---------- misc helpers ----------
__device__ __forceinline__ uint32_t smem_u32(const void* p) {
    uint32_t a;
    asm("{ .reg .u64 t; cvta.to.shared.u64 t, %1; cvt.u32.u64 %0, t; }"
        : "=r"(a) : "l"(p));
    return a;
}
__device__ __forceinline__ void split1(float x, __nv_bfloat16& h, __nv_bfloat16& l) {
    h = __float2bfloat16(x);
    l = __float2bfloat16(x - __bfloat162float(h));
}
__device__ __forceinline__ uint32_t redux_max_u32(uint32_t v) {
    uint32_t r;
    asm volatile("redux.sync.max.u32 %0, %1, 0xffffffff;" : "=r"(r) : "r"(v));
    return r;
}
// monotonic float->uint map (order-preserving)
__device__ __forceinline__ uint32_t f2u(float x) {
    uint32_t u = __float_as_uint(x);
    return u ^ (uint32_t)(((int32_t)u >> 31) | 0x80000000);
}
__device__ __forceinline__ float u2f(uint32_t u) {
    uint32_t x = (u >> 31) ? (u ^ 0x80000000u) : ~u;
    return __uint_as_float(x);
}
__device__ __forceinline__ void csw(uint32_t& a, uint32_t& b) {  // desc compare-swap
    uint32_t hi = max(a, b), lo = min(a, b);
    a = hi; b = lo;
}

// ---------- bf16 split pre-conversion kernels ----------
__global__ void __launch_bounds__(256) conv_h(const float* __restrict__ src) {
    size_t i = ((size_t)blockIdx.x * 256 + threadIdx.x) * 4;
    float4 f = *(const float4*)(src + i);
    __nv_bfloat16 h0,l0,h1,l1,h2,l2,h3,l3;
    split1(f.x,h0,l0); split1(f.y,h1,l1); split1(f.z,h2,l2); split1(f.w,h3,l3);
    ushort4 H = { __bfloat16_as_ushort(h0), __bfloat16_as_ushort(h1),
                  __bfloat16_as_ushort(h2), __bfloat16_as_ushort(h3) };
    ushort4 L = { __bfloat16_as_ushort(l0), __bfloat16_as_ushort(l1),
                  __bfloat16_as_ushort(l2), __bfloat16_as_ushort(l3) };
    *(ushort4*)(g_Hhi + i) = H;
    *(ushort4*)(g_Hlo + i) = L;
}

__global__ void __launch_bounds__(256) conv_w(const float* __restrict__ q,
                                              const float* __restrict__ k,
                                              const float* __restrict__ v,
                                              const float* __restrict__ o) {
    size_t i4 = (size_t)blockIdx.x * 256 + threadIdx.x;
    int w = (int)(i4 >> 16);
    const float* s = (w == 0) ? q : (w == 1) ? k : (w == 2) ? v : o;
    size_t loc = (i4 & 65535) * 4;
    size_t i = i4 * 4;
    float4 f = *(const float4*)(s + loc);
    __nv_bfloat16 h0,l0,h1,l1,h2,l2,h3,l3;
    split1(f.x,h0,l0); split1(f.y,h1,l1); split1(f.z,h2,l2); split1(f.w,h3,l3);
    ushort4 H = { __bfloat16_as_ushort(h0), __bfloat16_as_ushort(h1),
                  __bfloat16_as_ushort(h2), __bfloat16_as_ushort(h3) };
    ushort4 L = { __bfloat16_as_ushort(l0), __bfloat16_as_ushort(l1),
                  __bfloat16_as_ushort(l2), __bfloat16_as_ushort(l3) };
    *(ushort4*)(g_Whi + i) = H;
    *(ushort4*)(g_Wlo + i) = L;
}

// ---------- tensor-core GEMM (mma.sync bf16 hi/lo, 3-product split) ----------
#define STAGE_B   32768
#define GEMM_SMEM (3*STAGE_B)   // 3-stage ring, 96KB

__device__ __forceinline__ uint32_t swz(uint32_t off) {     // 64B rows
    return off ^ (((off >> 6) & 7) << 4);
}
__device__ __forceinline__ uint32_t swz128(uint32_t off) {  // 128B rows
    return off ^ (((off >> 7) & 7) << 4);
}

#define CPA16(dst, src) \
    asm volatile("cp.async.cg.shared.global [%0], [%1], 16;" :: "r"(dst), "l"(src))
#define CPCOMMIT() asm volatile("cp.async.commit_group;" ::: "memory")
#define CPWAIT(n)  asm volatile("cp.async.wait_group %0;" :: "n"(n) : "memory")

#define LDSM4(r, a) \
    asm volatile("ldmatrix.sync.aligned.m8n8.x4.shared.b16 {%0,%1,%2,%3}, [%4];" \
        : "=r"((r)[0]),"=r"((r)[1]),"=r"((r)[2]),"=r"((r)[3]) : "r"(a))

#define MMA16816(d, a, b0, b1) \
    asm volatile("mma.sync.aligned.m16n8k16.row.col.f32.bf16.bf16.f32 " \
        "{%0,%1,%2,%3},{%4,%5,%6,%7},{%8,%9},{%0,%1,%2,%3};" \
        : "+f"((d)[0]),"+f"((d)[1]),"+f"((d)[2]),"+f"((d)[3]) \
        : "r"((a)[0]),"r"((a)[1]),"r"((a)[2]),"r"((a)[3]), "r"(b0),"r"(b1))

// MODE 0: qkv (A=g_Hhi/lo, W = weight bx>>2, scatter: Q/K bf16 splits, V fp32)
// MODE 1: out-proj (A=g_Mhi/lo, W = Wo, out = residual(h) + A@Wo^T)
template <int MODE>
__global__ void __launch_bounds__(256, 2) gemm_mma(
    const float* __restrict__ hres, float* __restrict__ outp)
{
    extern __shared__ char sm[];
    uint32_t sb = smem_u32(sm);
    int tid = threadIdx.x, lane = tid & 31, wid = tid >> 5;
    int bx = blockIdx.x;
    int m0 = blockIdx.y * 128;
    int wsel, n0;
    if (MODE == 0) { wsel = bx >> 2; n0 = (bx & 3) * 128; }
    else           { wsel = 3;       n0 = bx * 128; }

    const __nv_bfloat16* Ahi = (MODE == 0) ? g_Hhi : g_Mhi;
    const __nv_bfloat16* Alo = (MODE == 0) ? g_Hlo : g_Mlo;
    const __nv_bfloat16* Bhi = g_Whi + (size_t)wsel * DM * DM;
    const __nv_bfloat16* Blo = g_Wlo + (size_t)wsel * DM * DM;

    auto loadc = [&](int c) {
        uint32_t stb = sb + (uint32_t)(c % 3) * STAGE_B;
#pragma unroll
        for (int i = 0; i < 8; i++) {
            int g = tid + i * 256;
            int tile = g >> 9;
            int idx = g & 511;
            int row = idx >> 2, kg = idx & 3;
            const __nv_bfloat16* src;
            if (tile == 0)      src = Ahi + (size_t)(m0 + row) * 512;
            else if (tile == 1) src = Alo + (size_t)(m0 + row) * 512;
            else if (tile == 2) src = Bhi + (size_t)(n0 + row) * 512;
            else                src = Blo + (size_t)(n0 + row) * 512;
            src += c * 32 + kg * 8;
            uint32_t dst = stb + tile * 8192 + swz((uint32_t)(row * 64 + kg * 16));
            CPA16(dst, src);
        }
        CPCOMMIT();
    };

    int wm = wid & 3, wn = wid >> 2;      // warp tile: 32(M) x 64(N)
    float acc[64];
#pragma unroll
    for (int i = 0; i < 64; i++) acc[i] = 0.f;

    loadc(0);
    loadc(1);
    for (int c = 0; c < 16; c++) {
        if (c == 15) { CPWAIT(0); } else { CPWAIT(1); }
        __syncthreads();                  // chunk c ready; slot (c+2)%3 free
        if (c + 2 < 16) loadc(c + 2);
        uint32_t stb = sb + (uint32_t)(c % 3) * STAGE_B;
#pragma unroll
        for (int ks = 0; ks < 2; ks++) {
            uint32_t ah[2][4], al[2][4];
#pragma unroll
            for (int mt = 0; mt < 2; mt++) {
                int r = wm * 32 + mt * 16 + (lane & 15);
                uint32_t off = swz((uint32_t)(r * 64 + (ks * 16 + (lane >> 4) * 8) * 2));
                LDSM4(ah[mt], stb + off);
                LDSM4(al[mt], stb + 8192 + off);
            }
#pragma unroll
            for (int p = 0; p < 4; p++) {
                int rr = wn * 64 + (2 * p + (lane >> 4)) * 8 + (lane & 7);
                uint32_t off = swz((uint32_t)(rr * 64 + (ks * 16 + ((lane >> 3) & 1) * 8) * 2));
                uint32_t bh[4], bl[4];
                LDSM4(bh, stb + 16384 + off);
                LDSM4(bl, stb + 24576 + off);
#pragma unroll
                for (int pr = 0; pr < 3; pr++) {
#pragma unroll
                    for (int mt = 0; mt < 2; mt++) {
#pragma unroll
                        for (int q = 0; q < 2; q++) {
                            float* d = acc + mt * 32 + (2 * p + q) * 4;
                            const uint32_t* a = (pr == 2) ? al[mt] : ah[mt];
                            const uint32_t* b = (pr == 1) ? bl : bh;
                            MMA16816(d, a, b[2 * q], b[2 * q + 1]);
                        }
                    }
                }
            }
        }
    }

    // ---- epilogue ----
#pragma unroll
    for (int mt = 0; mt < 2; mt++) {
#pragma unroll
        for (int half = 0; half < 2; half++) {
            int m = m0 + wm * 32 + mt * 16 + half * 8 + (lane >> 2);
            if (MODE == 0) {
                int b = m >> 13, v = (m >> 6) & 127, t = m & 63;
                int head = (n0 >> 6) + wn;
                size_t rb = (((size_t)(b * 64 + t) * 8 + head) * 128 + v) * 64
                            + (lane & 3) * 2;
#pragma unroll
                for (int nt = 0; nt < 8; nt++) {
                    int base = mt * 32 + nt * 4 + half * 2;
                    float2 val = make_float2(acc[base], acc[base + 1]);
                    size_t g = rb + nt * 8;
                    if (wsel == 2) {
                        *(float2*)&g_V[g] = val;
                    } else {
                        if (wsel == 0) { val.x *= 0.125f; val.y *= 0.125f; }
                        __nv_bfloat16 h0, l0, h1, l1;
                        split1(val.x, h0, l0);
                        split1(val.y, h1, l1);
                        ushort2 H = { __bfloat16_as_ushort(h0), __bfloat16_as_ushort(h1) };
                        ushort2 L = { __bfloat16_as_ushort(l0), __bfloat16_as_ushort(l1) };
                        if (wsel == 0) {
                            *(ushort2*)(g_Qhi + g) = H;
                            *(ushort2*)(g_Qlo + g) = L;
                        } else {
                            *(ushort2*)(g_Khi + g) = H;
                            *(ushort2*)(g_Klo + g) = L;
                        }
                    }
                }
            } else {
                int Bi = m >> 7, v = m & 127;
                int b = Bi >> 6, t = Bi & 63;
                size_t dbase = (((size_t)b * 128 + v) * 64 + t) * 512
                               + n0 + wn * 64 + (lane & 3) * 2;
#pragma unroll
                for (int nt = 0; nt < 8; nt++) {
                    int base = mt * 32 + nt * 4 + half * 2;
                    float2 val = make_float2(acc[base], acc[base + 1]);
                    size_t d = dbase + nt * 8;
                    float2 hv = *(const float2*)&hres[d];
                    val.x += hv.x; val.y += hv.y;
                    *(float2*)&outp[d] = val;
                }
            }
        }
    }
}

// =====================================================================
// Attention v5: tensor-core scores + 8-row-interleaved tournament top-16
// (latency-hiding across 8 independent redux chains) + smem sparse AV.
// One CTA per (B, head). 256 threads, 2 CTA/SM.
// =====================================================================
#define AOFF_QHI 0
#define AOFF_QLO 16384
#define AOFF_KHI 32768
#define AOFF_KLO 49152
#define AOFF_S   0                // overlays Q/K: fp32 [128][128] = 65536
#define AOFF_V   65536            // fp32 [128][64] = 32768
#define AOFF_PIDX 98304           // int  [128][16] = 8192
#define AOFF_PVAL 106496          // f32  [128][16] = 8192
#define ATT_SMEM 114688

// XOR bank-swizzled S index ([128][128] fp32)
__device__ __forceinline__ int sidx(int r, int c) {
    return r * 128 + (c ^ ((r & 7) << 2));
}

__device__ __forceinline__ void store_hl(size_t idx, float2 v) {
    __nv_bfloat16 h0, l0, h1, l1;
    split1(v.x, h0, l0);
    split1(v.y, h1, l1);
    ushort2 H = { __bfloat16_as_ushort(h0), __bfloat16_as_ushort(h1) };
    ushort2 L = { __bfloat16_as_ushort(l0), __bfloat16_as_ushort(l1) };
    *(ushort2*)(g_Mhi + idx) = H;
    *(ushort2*)(g_Mlo + idx) = L;
}

__global__ void __launch_bounds__(256, 2) attn2() {
    extern __shared__ char sm[];
    uint32_t sb = smem_u32(sm);
    float* sS = (float*)(sm + AOFF_S);
    int*   sPidx = (int*)(sm + AOFF_PIDX);
    float* sPval = (float*)(sm + AOFF_PVAL);
    float* sV = (float*)(sm + AOFF_V);

    int tid = threadIdx.x, lane = tid & 31, wid = tid >> 5;
    int bx = blockIdx.x;                 // B*8 + head
    size_t base = (size_t)bx * 8192;     // 128*64

    // zero compacted-P arrays (guard for duplicate-score edge case)
    for (int i = tid; i < 2048; i += 256) { sPidx[i] = 0; sPval[i] = 0.f; }

    // ---- async loads: Q/K bf16 tiles (swizzled 128B rows), V fp32 ----
#pragma unroll
    for (int i = 0; i < 4; i++) {
        int g = tid + i * 256;           // 0..1023
        int row = g >> 3, kg = g & 7;
        uint32_t doff = swz128((uint32_t)(row * 128 + kg * 16));
        CPA16(sb + AOFF_QHI + doff, g_Qhi + base + row * 64 + kg * 8);
        CPA16(sb + AOFF_QLO + doff, g_Qlo + base + row * 64 + kg * 8);
        CPA16(sb + AOFF_KHI + doff, g_Khi + base + row * 64 + kg * 8);
        CPA16(sb + AOFF_KLO + doff, g_Klo + base + row * 64 + kg * 8);
    }
#pragma unroll
    for (int i = 0; i < 8; i++) {
        int g = tid + i * 256;           // 0..2047 chunks of 16B
        CPA16(sb + AOFF_V + g * 16, g_V + base + g * 4);
    }
    CPCOMMIT();
    CPWAIT(0);
    __syncthreads();

    // ---- S = Q @ K^T via mma (3-product split). warp tile 64(M) x 32(N) ----
    {
        int wm = wid & 1, wn = wid >> 1;
        float acc[64];
#pragma unroll
        for (int i = 0; i < 64; i++) acc[i] = 0.f;
#pragma unroll
        for (int kt = 0; kt < 4; kt++) {
            uint32_t ah[4][4], al[4][4];
#pragma unroll
            for (int mt = 0; mt < 4; mt++) {
                int r = wm * 64 + mt * 16 + (lane & 15);
                uint32_t off = swz128((uint32_t)(r * 128 + (kt * 16 + (lane >> 4) * 8) * 2));
                LDSM4(ah[mt], sb + AOFF_QHI + off);
                LDSM4(al[mt], sb + AOFF_QLO + off);
            }
#pragma unroll
            for (int p = 0; p < 2; p++) {
                int rr = wn * 32 + (2 * p + (lane >> 4)) * 8 + (lane & 7);
                uint32_t off = swz128((uint32_t)(rr * 128 + (kt * 16 + ((lane >> 3) & 1) * 8) * 2));
                uint32_t bh[4], bl[4];
                LDSM4(bh, sb + AOFF_KHI + off);
                LDSM4(bl, sb + AOFF_KLO + off);
#pragma unroll
                for (int pr = 0; pr < 3; pr++) {
#pragma unroll
                    for (int mt = 0; mt < 4; mt++) {
#pragma unroll
                        for (int q = 0; q < 2; q++) {
                            float* d = acc + mt * 16 + (2 * p + q) * 4;
                            const uint32_t* a = (pr == 2) ? al[mt] : ah[mt];
                            const uint32_t* b = (pr == 1) ? bl : bh;
                            MMA16816(d, a, b[2 * q], b[2 * q + 1]);
                        }
                    }
                }
            }
        }
        __syncthreads();   // all warps done reading Q/K before S overwrites them
        // store S to overlaid SMEM [128][128] with XOR swizzle
#pragma unroll
        for (int mt = 0; mt < 4; mt++) {
#pragma unroll
            for (int half = 0; half < 2; half++) {
                int r = wm * 64 + mt * 16 + half * 8 + (lane >> 2);
#pragma unroll
                for (int nt = 0; nt < 4; nt++) {
                    int col = wn * 32 + nt * 8 + (lane & 3) * 2;
                    int bi = mt * 16 + nt * 4 + half * 2;
                    *(float2*)&sS[sidx(r, col)] = make_float2(acc[bi], acc[bi + 1]);
                }
            }
        }
    }
    __syncthreads();

    // ---- top-16: 8 independent rows interleaved (latency-hidden) ----
    for (int half = 0; half < 2; half++) {
        int rbase = wid * 16 + half * 8;
        uint32_t u[8][4];
#pragma unroll
        for (int j = 0; j < 8; j++) {
            float4 f = *(float4*)&sS[sidx(rbase + j, lane * 4)];
            u[j][0] = f2u(f.x); u[j][1] = f2u(f.y);
            u[j][2] = f2u(f.z); u[j][3] = f2u(f.w);
            // per-lane descending sort (sorting network)
            csw(u[j][0], u[j][2]); csw(u[j][1], u[j][3]);
            csw(u[j][0], u[j][1]); csw(u[j][2], u[j][3]); csw(u[j][1], u[j][2]);
        }
        uint32_t th[8];
        float rm[8];
#pragma unroll
        for (int j = 0; j < 8; j++) {
            uint32_t g = redux_max_u32(u[j][0]);
            th[j] = g;
            rm[j] = u2f(g);
            bool t = (u[j][0] == g);
            u[j][0] = t ? u[j][1] : u[j][0];
            u[j][1] = t ? u[j][2] : u[j][1];
            u[j][2] = t ? u[j][3] : u[j][2];
            u[j][3] = t ? 0u      : u[j][3];
        }
#pragma unroll 1
        for (int it = 1; it < TOPKN; it++) {
#pragma unroll
            for (int j = 0; j < 8; j++) {
                uint32_t g = redux_max_u32(u[j][0]);
                th[j] = g;
                bool t = (u[j][0] == g);
                u[j][0] = t ? u[j][1] : u[j][0];
                u[j][1] = t ? u[j][2] : u[j][1];
                u[j][2] = t ? u[j][3] : u[j][2];
                u[j][3] = t ? 0u      : u[j][3];
            }
        }
        // softmax + compaction per row (re-read S from smem)
#pragma unroll
        for (int j = 0; j < 8; j++) {
            int r = rbase + j;
            float4 f = *(float4*)&sS[sidx(r, lane * 4)];
            float fa[4] = { f.x, f.y, f.z, f.w };
            float p[4];
            float s = 0.f;
#pragma unroll
            for (int e = 0; e < 4; e++) {
                p[e] = (f2u(fa[e]) >= th[j]) ? __expf(fa[e] - rm[j]) : 0.f;
                s += p[e];
            }
#pragma unroll
            for (int o = 16; o; o >>= 1)
                s += __shfl_xor_sync(FULLMASK, s, o);
            float inv = 1.0f / s;
            int bc = 0;
            uint32_t lt = (1u << lane) - 1u;
#pragma unroll
            for (int e = 0; e < 4; e++) {
                uint32_t b = __ballot_sync(FULLMASK, p[e] > 0.f);
                if (p[e] > 0.f) {
                    int pos = bc + __popc(b & lt);
                    if (pos < 16) {
                        sPidx[r * 16 + pos] = lane * 4 + e;
                        sPval[r * 16 + pos] = p[e] * inv;
                    }
                }
                bc += __popc(b);
            }
        }
    }
    __syncthreads();

    // ---- sparse AV: mixed[r] = sum_j p_j * V[idx_j]  (lane owns 2 cols) ----
    int B = bx >> 3, hh = bx & 7;
    for (int i = 0; i < 8; i++) {
        int r0 = wid * 16 + 2 * i;
        int r1 = r0 + 1;
        unsigned long long a0 = 0, a1 = 0;
#pragma unroll
        for (int j = 0; j < 16; j++) {
            int i0 = sPidx[r0 * 16 + j];
            int i1 = sPidx[r1 * 16 + j];
            float q0 = sPval[r0 * 16 + j];
            float q1 = sPval[r1 * 16 + j];
            unsigned long long v0 = *(unsigned long long*)&sV[i0 * 64 + lane * 2];
            unsigned long long v1 = *(unsigned long long*)&sV[i1 * 64 + lane * 2];
            a0 = fma2(pack2(q0, q0), v0, a0);
            a1 = fma2(pack2(q1, q1), v1, a1);
        }
        size_t o0 = ((size_t)B * 128 + r0) * 512 + hh * 64 + lane * 2;
        store_hl(o0, unpack2(a0));
        store_hl(o0 + 512, unpack2(a1));
    }
}

// =====================================================================
extern "C" void kernel_launch(void* const* d_in, const int* in_sizes, int n_in,
                              void* d_out, int out_size) {
    const float* h  = (const float*)d_in[0];
    const float* Wq = (const float*)d_in[1];
    const float* Wk = (const float*)d_in[2];
    const float* Wv = (const float*)d_in[3];
    const float* Wo = (const float*)d_in[4];
    float* out = (float*)d_out;

    cudaFuncSetAttribute(gemm_mma<0>, cudaFuncAttributeMaxDynamicSharedMemorySize, GEMM_SMEM);
    cudaFuncSetAttribute(gemm_mma<1>, cudaFuncAttributeMaxDynamicSharedMemorySize, GEMM_SMEM);
    cudaFuncSetAttribute(attn2, cudaFuncAttributeMaxDynamicSharedMemorySize, ATT_SMEM);

    conv_h<<<65536, 256>>>(h);
    conv_w<<<1024, 256>>>(Wq, Wk, Wv, Wo);
    gemm_mma<0><<<dim3(12, 1024), 256, GEMM_SMEM>>>(nullptr, nullptr);
    attn2<<<8192, 256, ATT_SMEM>>>();
    gemm_mma<1><<<dim3(4, 1024), 256, GEMM_SMEM>>>(h, out);
}

// round 9
// speedup vs baseline: 1.0401x; 1.0401x over previous
#include <cuda_runtime.h>
#include <cuda_bf16.h>
#include <cstdint>

// Problem dims
#define BSZ 16
#define NV  128
#define NT  64
#define DM  512
#define HEADS 8
#define HD  64
#define TOPKN 16
#define BATT (BSZ*NT)          // 1024
#define FULLMASK 0xffffffffu

#define HN ((size_t)BSZ*NV*NT*DM)   // 67,108,864 elements
#define QKN ((size_t)BATT*HEADS*NV*HD)

// ---------- scratch (device globals; no allocation allowed) ----------
__device__ __nv_bfloat16 g_Qhi[QKN];    // [B][H][V][hd], pre-scaled by 1/8
__device__ __nv_bfloat16 g_Qlo[QKN];
__device__ __nv_bfloat16 g_Khi[QKN];
__device__ __nv_bfloat16 g_Klo[QKN];
__device__ float g_V[QKN];              // [B][H][V][hd] fp32
__device__ __nv_bfloat16 g_Hhi[HN];     // h split hi  [m][k], m=(b*128+v)*64+t
__device__ __nv_bfloat16 g_Hlo[HN];
__device__ __nv_bfloat16 g_Mhi[HN];     // mixed bf16 [m][k], m=(b*64+t)*128+v
__device__ __nv_bfloat16 g_Whi[4*DM*DM];  // Wq,Wk,Wv,Wo split hi [n][k]
__device__ __nv_bfloat16 g_Wlo[4*DM*DM];

// ---------- packed f32x2 helpers ----------
__device__ __forceinline__ unsigned long long pack2(float lo, float hi) {
    unsigned long long r;
    asm("mov.b64 %0, {%1, %2};" : "=l"(r) : "f"(lo), "f"(hi));
    return r;
}
__device__ __forceinline__ float2 unpack2(unsigned long long v) {
    float2 r;
    asm("mov.b64 {%0, %1}, %2;" : "=f"(r.x), "=f"(r.y) : "l"(v));
    return r;
}
__device__ __forceinline__ unsigned long long fma2(unsigned long long a,
                                                   unsigned long long b,
                                                   unsigned long long c) {
    unsigned long long d;
    asm("fma.rn.f32x2 %0, %1, %2, %3;" : "=l"(d) : "l"(a), "l"(b), "l"(c));
    return d;
}

// ---------- misc helpers ----------
__device__ __forceinline__ uint32_t smem_u32(const void* p) {
    uint32_t a;
    asm("{ .reg .u64 t; cvta.to.shared.u64 t, %1; cvt.u32.u64 %0, t; }"
        : "=r"(a) : "l"(p));
    return a;
}
__device__ __forceinline__ void split1(float x, __nv_bfloat16& h, __nv_bfloat16& l) {
    h = __float2bfloat16(x);
    l = __float2bfloat16(x - __bfloat162float(h));
}
__device__ __forceinline__ uint32_t redux_max_u32(uint32_t v) {
    uint32_t r;
    asm volatile("redux.sync.max.u32 %0, %1, 0xffffffff;" : "=r"(r) : "r"(v));
    return r;
}
// monotonic float->uint map (order-preserving)
__device__ __forceinline__ uint32_t f2u(float x) {
    uint32_t u = __float_as_uint(x);
    return u ^ (uint32_t)(((int32_t)u >> 31) | 0x80000000);
}
__device__ __forceinline__ float u2f(uint32_t u) {
    uint32_t x = (u >> 31) ? (u ^ 0x80000000u) : ~u;
    return __uint_as_float(x);
}
__device__ __forceinline__ void csw(uint32_t& a, uint32_t& b) {  // desc compare-swap
    uint32_t hi = max(a, b), lo = min(a, b);
    a = hi; b = lo;
}

// ---------- bf16 split pre-conversion kernels ----------
__global__ void __launch_bounds__(256) conv_h(const float* __restrict__ src) {
    size_t i = ((size_t)blockIdx.x * 256 + threadIdx.x) * 4;
    float4 f = *(const float4*)(src + i);
    __nv_bfloat16 h0,l0,h1,l1,h2,l2,h3,l3;
    split1(f.x,h0,l0); split1(f.y,h1,l1); split1(f.z,h2,l2); split1(f.w,h3,l3);
    ushort4 H = { __bfloat16_as_ushort(h0), __bfloat16_as_ushort(h1),
                  __bfloat16_as_ushort(h2), __bfloat16_as_ushort(h3) };
    ushort4 L = { __bfloat16_as_ushort(l0), __bfloat16_as_ushort(l1),
                  __bfloat16_as_ushort(l2), __bfloat16_as_ushort(l3) };
    *(ushort4*)(g_Hhi + i) = H;
    *(ushort4*)(g_Hlo + i) = L;
}

__global__ void __launch_bounds__(256) conv_w(const float* __restrict__ q,
                                              const float* __restrict__ k,
                                              const float* __restrict__ v,
                                              const float* __restrict__ o) {
    size_t i4 = (size_t)blockIdx.x * 256 + threadIdx.x;
    int w = (int)(i4 >> 16);
    const float* s = (w == 0) ? q : (w == 1) ? k : (w == 2) ? v : o;
    size_t loc = (i4 & 65535) * 4;
    size_t i = i4 * 4;
    float4 f = *(const float4*)(s + loc);
    __nv_bfloat16 h0,l0,h1,l1,h2,l2,h3,l3;
    split1(f.x,h0,l0); split1(f.y,h1,l1); split1(f.z,h2,l2); split1(f.w,h3,l3);
    ushort4 H = { __bfloat16_as_ushort(h0), __bfloat16_as_ushort(h1),
                  __bfloat16_as_ushort(h2), __bfloat16_as_ushort(h3) };
    ushort4 L = { __bfloat16_as_ushort(l0), __bfloat16_as_ushort(l1),
                  __bfloat16_as_ushort(l2), __bfloat16_as_ushort(l3) };
    *(ushort4*)(g_Whi + i) = H;
    *(ushort4*)(g_Wlo + i) = L;
}

// ---------- tensor-core GEMM (mma.sync bf16 hi/lo split) ----------
#define STAGE_B   32768
#define GEMM_SMEM (3*STAGE_B)   // 3-stage ring, 96KB

__device__ __forceinline__ uint32_t swz(uint32_t off) {     // 64B rows
    return off ^ (((off >> 6) & 7) << 4);
}
__device__ __forceinline__ uint32_t swz128(uint32_t off) {  // 128B rows
    return off ^ (((off >> 7) & 7) << 4);
}

#define CPA16(dst, src) \
    asm volatile("cp.async.cg.shared.global [%0], [%1], 16;" :: "r"(dst), "l"(src))
#define CPCOMMIT() asm volatile("cp.async.commit_group;" ::: "memory")
#define CPWAIT(n)  asm volatile("cp.async.wait_group %0;" :: "n"(n) : "memory")

#define LDSM4(r, a) \
    asm volatile("ldmatrix.sync.aligned.m8n8.x4.shared.b16 {%0,%1,%2,%3}, [%4];" \
        : "=r"((r)[0]),"=r"((r)[1]),"=r"((r)[2]),"=r"((r)[3]) : "r"(a))

#define MMA16816(d, a, b0, b1) \
    asm volatile("mma.sync.aligned.m16n8k16.row.col.f32.bf16.bf16.f32 " \
        "{%0,%1,%2,%3},{%4,%5,%6,%7},{%8,%9},{%0,%1,%2,%3};" \
        : "+f"((d)[0]),"+f"((d)[1]),"+f"((d)[2]),"+f"((d)[3]) \
        : "r"((a)[0]),"r"((a)[1]),"r"((a)[2]),"r"((a)[3]), "r"(b0),"r"(b1))

// MODE 0: qkv (A=g_Hhi/lo, W = weight bx>>2). Q/K use 3 products; V uses 2.
// MODE 1: out-proj (A=g_Mhi only, W = Wo, 2 products, + residual)
template <int MODE>
__global__ void __launch_bounds__(256, 2) gemm_mma(
    const float* __restrict__ hres, float* __restrict__ outp)
{
    extern __shared__ char sm[];
    uint32_t sb = smem_u32(sm);
    int tid = threadIdx.x, lane = tid & 31, wid = tid >> 5;
    int bx = blockIdx.x;
    int m0 = blockIdx.y * 128;
    int wsel, n0;
    if (MODE == 0) { wsel = bx >> 2; n0 = (bx & 3) * 128; }
    else           { wsel = 3;       n0 = bx * 128; }

    const bool useAlo = (MODE == 0) && (wsel != 2);   // CTA-uniform

    const __nv_bfloat16* Ahi = (MODE == 0) ? g_Hhi : g_Mhi;
    const __nv_bfloat16* Alo = (MODE == 0) ? g_Hlo : g_Mhi;  // MODE1: dup (unused)
    const __nv_bfloat16* Bhi = g_Whi + (size_t)wsel * DM * DM;
    const __nv_bfloat16* Blo = g_Wlo + (size_t)wsel * DM * DM;

    auto loadc = [&](int c) {
        uint32_t stb = sb + (uint32_t)(c % 3) * STAGE_B;
#pragma unroll
        for (int i = 0; i < 8; i++) {
            int g = tid + i * 256;
            int tile = g >> 9;
            int idx = g & 511;
            int row = idx >> 2, kg = idx & 3;
            const __nv_bfloat16* src;
            if (tile == 0)      src = Ahi + (size_t)(m0 + row) * 512;
            else if (tile == 1) src = Alo + (size_t)(m0 + row) * 512;
            else if (tile == 2) src = Bhi + (size_t)(n0 + row) * 512;
            else                src = Blo + (size_t)(n0 + row) * 512;
            src += c * 32 + kg * 8;
            uint32_t dst = stb + tile * 8192 + swz((uint32_t)(row * 64 + kg * 16));
            CPA16(dst, src);
        }
        CPCOMMIT();
    };

    int wm = wid & 3, wn = wid >> 2;      // warp tile: 32(M) x 64(N)
    float acc[64];
#pragma unroll
    for (int i = 0; i < 64; i++) acc[i] = 0.f;

    loadc(0);
    loadc(1);
    for (int c = 0; c < 16; c++) {
        if (c == 15) { CPWAIT(0); } else { CPWAIT(1); }
        __syncthreads();                  // chunk c ready; slot (c+2)%3 free
        if (c + 2 < 16) loadc(c + 2);
        uint32_t stb = sb + (uint32_t)(c % 3) * STAGE_B;
#pragma unroll
        for (int ks = 0; ks < 2; ks++) {
            uint32_t ah[2][4];
            uint32_t al[2][4] = {{0,0,0,0},{0,0,0,0}};
#pragma unroll
            for (int mt = 0; mt < 2; mt++) {
                int r = wm * 32 + mt * 16 + (lane & 15);
                uint32_t off = swz((uint32_t)(r * 64 + (ks * 16 + (lane >> 4) * 8) * 2));
                LDSM4(ah[mt], stb + off);
                if (useAlo) LDSM4(al[mt], stb + 8192 + off);
            }
#pragma unroll
            for (int p = 0; p < 4; p++) {
                int rr = wn * 64 + (2 * p + (lane >> 4)) * 8 + (lane & 7);
                uint32_t off = swz((uint32_t)(rr * 64 + (ks * 16 + ((lane >> 3) & 1) * 8) * 2));
                uint32_t bh[4], bl[4];
                LDSM4(bh, stb + 16384 + off);
                LDSM4(bl, stb + 24576 + off);
#pragma unroll
                for (int pr = 0; pr < 3; pr++) {
                    if (pr == 2 && !useAlo) continue;   // V / out-proj: 2 products
#pragma unroll
                    for (int mt = 0; mt < 2; mt++) {
#pragma unroll
                        for (int q = 0; q < 2; q++) {
                            float* d = acc + mt * 32 + (2 * p + q) * 4;
                            const uint32_t* a = (pr == 2) ? al[mt] : ah[mt];
                            const uint32_t* b = (pr == 1) ? bl : bh;
                            MMA16816(d, a, b[2 * q], b[2 * q + 1]);
                        }
                    }
                }
            }
        }
    }

    // ---- epilogue ----
#pragma unroll
    for (int mt = 0; mt < 2; mt++) {
#pragma unroll
        for (int half = 0; half < 2; half++) {
            int m = m0 + wm * 32 + mt * 16 + half * 8 + (lane >> 2);
            if (MODE == 0) {
                int b = m >> 13, v = (m >> 6) & 127, t = m & 63;
                int head = (n0 >> 6) + wn;
                size_t rb = (((size_t)(b * 64 + t) * 8 + head) * 128 + v) * 64
                            + (lane & 3) * 2;
#pragma unroll
                for (int nt = 0; nt < 8; nt++) {
                    int base = mt * 32 + nt * 4 + half * 2;
                    float2 val = make_float2(acc[base], acc[base + 1]);
                    size_t g = rb + nt * 8;
                    if (wsel == 2) {
                        *(float2*)&g_V[g] = val;
                    } else {
                        if (wsel == 0) { val.x *= 0.125f; val.y *= 0.125f; }
                        __nv_bfloat16 h0, l0, h1, l1;
                        split1(val.x, h0, l0);
                        split1(val.y, h1, l1);
                        ushort2 H = { __bfloat16_as_ushort(h0), __bfloat16_as_ushort(h1) };
                        ushort2 L = { __bfloat16_as_ushort(l0), __bfloat16_as_ushort(l1) };
                        if (wsel == 0) {
                            *(ushort2*)(g_Qhi + g) = H;
                            *(ushort2*)(g_Qlo + g) = L;
                        } else {
                            *(ushort2*)(g_Khi + g) = H;
                            *(ushort2*)(g_Klo + g) = L;
                        }
                    }
                }
            } else {
                int Bi = m >> 7, v = m & 127;
                int b = Bi >> 6, t = Bi & 63;
                size_t dbase = (((size_t)b * 128 + v) * 64 + t) * 512
                               + n0 + wn * 64 + (lane & 3) * 2;
#pragma unroll
                for (int nt = 0; nt < 8; nt++) {
                    int base = mt * 32 + nt * 4 + half * 2;
                    float2 val = make_float2(acc[base], acc[base + 1]);
                    size_t d = dbase + nt * 8;
                    float2 hv = *(const float2*)&hres[d];
                    val.x += hv.x; val.y += hv.y;
                    *(float2*)&outp[d] = val;
                }
            }
        }
    }
}

// =====================================================================
// Attention v4 (round-7 proven): tensor-core scores + sorted-tournament
// top-16 + smem-compacted sparse AV. mixed stored as bf16 hi only.
// =====================================================================
#define AOFF_QHI 0
#define AOFF_QLO 16384
#define AOFF_KHI 32768
#define AOFF_KLO 49152
#define AOFF_S   0                // overlays Q/K: fp32 [128][128] = 65536
#define AOFF_V   65536            // fp32 [128][64] = 32768
#define AOFF_PIDX 98304           // int  [128][16] = 8192
#define AOFF_PVAL 106496          // f32  [128][16] = 8192
#define ATT_SMEM 114688

// XOR bank-swizzled S index ([128][128] fp32)
__device__ __forceinline__ int sidx(int r, int c) {
    return r * 128 + (c ^ ((r & 7) << 2));
}

__device__ __forceinline__ void store_h(size_t idx, float2 v) {
    ushort2 H = { __bfloat16_as_ushort(__float2bfloat16(v.x)),
                  __bfloat16_as_ushort(__float2bfloat16(v.y)) };
    *(ushort2*)(g_Mhi + idx) = H;
}

__global__ void __launch_bounds__(256, 2) attn2() {
    extern __shared__ char sm[];
    uint32_t sb = smem_u32(sm);
    float* sS = (float*)(sm + AOFF_S);
    int*   sPidx = (int*)(sm + AOFF_PIDX);
    float* sPval = (float*)(sm + AOFF_PVAL);
    float* sV = (float*)(sm + AOFF_V);

    int tid = threadIdx.x, lane = tid & 31, wid = tid >> 5;
    int bx = blockIdx.x;                 // B*8 + head
    size_t base = (size_t)bx * 8192;     // 128*64

    // zero compacted-P arrays (guard for duplicate-score edge case)
    for (int i = tid; i < 2048; i += 256) { sPidx[i] = 0; sPval[i] = 0.f; }

    // ---- async loads: Q/K bf16 tiles (swizzled 128B rows), V fp32 ----
#pragma unroll
    for (int i = 0; i < 4; i++) {
        int g = tid + i * 256;           // 0..1023
        int row = g >> 3, kg = g & 7;
        uint32_t doff = swz128((uint32_t)(row * 128 + kg * 16));
        CPA16(sb + AOFF_QHI + doff, g_Qhi + base + row * 64 + kg * 8);
        CPA16(sb + AOFF_QLO + doff, g_Qlo + base + row * 64 + kg * 8);
        CPA16(sb + AOFF_KHI + doff, g_Khi + base + row * 64 + kg * 8);
        CPA16(sb + AOFF_KLO + doff, g_Klo + base + row * 64 + kg * 8);
    }
#pragma unroll
    for (int i = 0; i < 8; i++) {
        int g = tid + i * 256;           // 0..2047 chunks of 16B
        CPA16(sb + AOFF_V + g * 16, g_V + base + g * 4);
    }
    CPCOMMIT();
    CPWAIT(0);
    __syncthreads();

    // ---- S = Q @ K^T via mma (3-product split). warp tile 64(M) x 32(N) ----
    {
        int wm = wid & 1, wn = wid >> 1;
        float acc[64];
#pragma unroll
        for (int i = 0; i < 64; i++) acc[i] = 0.f;
#pragma unroll
        for (int kt = 0; kt < 4; kt++) {
            uint32_t ah[4][4], al[4][4];
#pragma unroll
            for (int mt = 0; mt < 4; mt++) {
                int r = wm * 64 + mt * 16 + (lane & 15);
                uint32_t off = swz128((uint32_t)(r * 128 + (kt * 16 + (lane >> 4) * 8) * 2));
                LDSM4(ah[mt], sb + AOFF_QHI + off);
                LDSM4(al[mt], sb + AOFF_QLO + off);
            }
#pragma unroll
            for (int p = 0; p < 2; p++) {
                int rr = wn * 32 + (2 * p + (lane >> 4)) * 8 + (lane & 7);
                uint32_t off = swz128((uint32_t)(rr * 128 + (kt * 16 + ((lane >> 3) & 1) * 8) * 2));
                uint32_t bh[4], bl[4];
                LDSM4(bh, sb + AOFF_KHI + off);
                LDSM4(bl, sb + AOFF_KLO + off);
#pragma unroll
                for (int pr = 0; pr < 3; pr++) {
#pragma unroll
                    for (int mt = 0; mt < 4; mt++) {
#pragma unroll
                        for (int q = 0; q < 2; q++) {
                            float* d = acc + mt * 16 + (2 * p + q) * 4;
                            const uint32_t* a = (pr == 2) ? al[mt] : ah[mt];
                            const uint32_t* b = (pr == 1) ? bl : bh;
                            MMA16816(d, a, b[2 * q], b[2 * q + 1]);
                        }
                    }
                }
            }
        }
        __syncthreads();   // all warps done reading Q/K before S overwrites them
        // store S to overlaid SMEM [128][128] with XOR swizzle
#pragma unroll
        for (int mt = 0; mt < 4; mt++) {
#pragma unroll
            for (int half = 0; half < 2; half++) {
                int r = wm * 64 + mt * 16 + half * 8 + (lane >> 2);
#pragma unroll
                for (int nt = 0; nt < 4; nt++) {
                    int col = wn * 32 + nt * 8 + (lane & 3) * 2;
                    int bi = mt * 16 + nt * 4 + half * 2;
                    *(float2*)&sS[sidx(r, col)] = make_float2(acc[bi], acc[bi + 1]);
                }
            }
        }
    }
    __syncthreads();

    // ---- top-16 (sorted tournament) + softmax, warp per 2 rows ----
    for (int i = 0; i < 8; i++) {
        int r0 = wid * 16 + 2 * i;
        int r1 = r0 + 1;
        float4 f0 = *(float4*)&sS[sidx(r0, lane * 4)];
        float4 f1 = *(float4*)&sS[sidx(r1, lane * 4)];
        float fa0[4] = { f0.x, f0.y, f0.z, f0.w };
        float fa1[4] = { f1.x, f1.y, f1.z, f1.w };
        uint32_t uo0[4], uo1[4], u0[4], u1[4];
#pragma unroll
        for (int e = 0; e < 4; e++) {
            uo0[e] = u0[e] = f2u(fa0[e]);
            uo1[e] = u1[e] = f2u(fa1[e]);
        }
        // per-lane descending sort of 4 values (sorting network)
        csw(u0[0], u0[2]); csw(u0[1], u0[3]);
        csw(u0[0], u0[1]); csw(u0[2], u0[3]); csw(u0[1], u0[2]);
        csw(u1[0], u1[2]); csw(u1[1], u1[3]);
        csw(u1[0], u1[1]); csw(u1[2], u1[3]); csw(u1[1], u1[2]);

        float rm0 = 0.f, rm1 = 0.f;
        uint32_t th0 = 0, th1 = 0;
#pragma unroll 1
        for (int it = 0; it < TOPKN; it++) {
            uint32_t g0 = redux_max_u32(u0[0]);
            uint32_t g1 = redux_max_u32(u1[0]);
            if (it == 0) { rm0 = u2f(g0); rm1 = u2f(g1); }
            th0 = g0; th1 = g1;
            bool t0 = (u0[0] == g0);
            bool t1 = (u1[0] == g1);
            u0[0] = t0 ? u0[1] : u0[0];
            u0[1] = t0 ? u0[2] : u0[1];
            u0[2] = t0 ? u0[3] : u0[2];
            u0[3] = t0 ? 0u    : u0[3];
            u1[0] = t1 ? u1[1] : u1[0];
            u1[1] = t1 ? u1[2] : u1[1];
            u1[2] = t1 ? u1[3] : u1[2];
            u1[3] = t1 ? 0u    : u1[3];
        }
        float p0[4], p1[4];
        float s0 = 0.f, s1 = 0.f;
#pragma unroll
        for (int e = 0; e < 4; e++) {
            p0[e] = (uo0[e] >= th0) ? __expf(fa0[e] - rm0) : 0.f;
            p1[e] = (uo1[e] >= th1) ? __expf(fa1[e] - rm1) : 0.f;
            s0 += p0[e]; s1 += p1[e];
        }
#pragma unroll
        for (int o = 16; o; o >>= 1) {
            s0 += __shfl_xor_sync(FULLMASK, s0, o);
            s1 += __shfl_xor_sync(FULLMASK, s1, o);
        }
        float inv0 = 1.0f / s0, inv1 = 1.0f / s1;
        // compact (idx, p) into 16-entry lists
        int bc0 = 0, bc1 = 0;
#pragma unroll
        for (int e = 0; e < 4; e++) {
            uint32_t b0 = __ballot_sync(FULLMASK, p0[e] > 0.f);
            uint32_t b1 = __ballot_sync(FULLMASK, p1[e] > 0.f);
            uint32_t lt = (1u << lane) - 1u;
            if (p0[e] > 0.f) {
                int pos = bc0 + __popc(b0 & lt);
                if (pos < 16) { sPidx[r0 * 16 + pos] = lane * 4 + e;
                                sPval[r0 * 16 + pos] = p0[e] * inv0; }
            }
            if (p1[e] > 0.f) {
                int pos = bc1 + __popc(b1 & lt);
                if (pos < 16) { sPidx[r1 * 16 + pos] = lane * 4 + e;
                                sPval[r1 * 16 + pos] = p1[e] * inv1; }
            }
            bc0 += __popc(b0);
            bc1 += __popc(b1);
        }
    }
    __syncthreads();

    // ---- sparse AV: mixed[r] = sum_j p_j * V[idx_j]  (lane owns 2 cols) ----
    int B = bx >> 3, hh = bx & 7;
    for (int i = 0; i < 8; i++) {
        int r0 = wid * 16 + 2 * i;
        int r1 = r0 + 1;
        unsigned long long a0 = 0, a1 = 0;
#pragma unroll
        for (int j = 0; j < 16; j++) {
            int i0 = sPidx[r0 * 16 + j];
            int i1 = sPidx[r1 * 16 + j];
            float q0 = sPval[r0 * 16 + j];
            float q1 = sPval[r1 * 16 + j];
            unsigned long long v0 = *(unsigned long long*)&sV[i0 * 64 + lane * 2];
            unsigned long long v1 = *(unsigned long long*)&sV[i1 * 64 + lane * 2];
            a0 = fma2(pack2(q0, q0), v0, a0);
            a1 = fma2(pack2(q1, q1), v1, a1);
        }
        size_t o0 = ((size_t)B * 128 + r0) * 512 + hh * 64 + lane * 2;
        store_h(o0, unpack2(a0));
        store_h(o0 + 512, unpack2(a1));
    }
}

// =====================================================================
extern "C" void kernel_launch(void* const* d_in, const int* in_sizes, int n_in,
                              void* d_out, int out_size) {
    const float* h  = (const float*)d_in[0];
    const float* Wq = (const float*)d_in[1];
    const float* Wk = (const float*)d_in[2];
    const float* Wv = (const float*)d_in[3];
    const float* Wo = (const float*)d_in[4];
    float* out = (float*)d_out;

    cudaFuncSetAttribute(gemm_mma<0>, cudaFuncAttributeMaxDynamicSharedMemorySize, GEMM_SMEM);
    cudaFuncSetAttribute(gemm_mma<1>, cudaFuncAttributeMaxDynamicSharedMemorySize, GEMM_SMEM);
    cudaFuncSetAttribute(attn2, cudaFuncAttributeMaxDynamicSharedMemorySize, ATT_SMEM);

    conv_h<<<65536, 256>>>(h);
    conv_w<<<1024, 256>>>(Wq, Wk, Wv, Wo);
    gemm_mma<0><<<dim3(12, 1024), 256, GEMM_SMEM>>>(nullptr, nullptr);
    attn2<<<8192, 256, ATT_SMEM>>>();
    gemm_mma<1><<<dim3(4, 1024), 256, GEMM_SMEM>>>(h, out);
}

// round 10
// speedup vs baseline: 1.1148x; 1.0717x over previous
#include <cuda_runtime.h>
#include <cuda_bf16.h>
#include <cstdint>

// Problem dims
#define BSZ 16
#define NV  128
#define NT  64
#define DM  512
#define HEADS 8
#define HD  64
#define TOPKN 16
#define BATT (BSZ*NT)          // 1024
#define FULLMASK 0xffffffffu

#define HN ((size_t)BSZ*NV*NT*DM)   // 67,108,864 elements
#define QKN ((size_t)BATT*HEADS*NV*HD)

// ---------- scratch (device globals; no allocation allowed) ----------
__device__ __nv_bfloat16 g_Qhi[QKN];    // [B][H][V][hd], pre-scaled by 1/8
__device__ __nv_bfloat16 g_Qlo[QKN];
__device__ __nv_bfloat16 g_Khi[QKN];
__device__ __nv_bfloat16 g_Klo[QKN];
__device__ __nv_bfloat16 g_Vb[QKN];     // [B][H][V][hd] bf16
__device__ __nv_bfloat16 g_Hhi[HN];     // h split hi  [m][k], m=(b*128+v)*64+t
__device__ __nv_bfloat16 g_Hlo[HN];
__device__ __nv_bfloat16 g_Mhi[HN];     // mixed bf16 [m][k], m=(b*64+t)*128+v
__device__ __nv_bfloat16 g_Whi[4*DM*DM];  // Wq,Wk,Wv,Wo split hi [n][k]
__device__ __nv_bfloat16 g_Wlo[4*DM*DM];

// ---------- packed f32x2 helpers ----------
__device__ __forceinline__ unsigned long long pack2(float lo, float hi) {
    unsigned long long r;
    asm("mov.b64 %0, {%1, %2};" : "=l"(r) : "f"(lo), "f"(hi));
    return r;
}
__device__ __forceinline__ float2 unpack2(unsigned long long v) {
    float2 r;
    asm("mov.b64 {%0, %1}, %2;" : "=f"(r.x), "=f"(r.y) : "l"(v));
    return r;
}
__device__ __forceinline__ unsigned long long fma2(unsigned long long a,
                                                   unsigned long long b,
                                                   unsigned long long c) {
    unsigned long long d;
    asm("fma.rn.f32x2 %0, %1, %2, %3;" : "=l"(d) : "l"(a), "l"(b), "l"(c));
    return d;
}

// ---------- misc helpers ----------
__device__ __forceinline__ uint32_t smem_u32(const void* p) {
    uint32_t a;
    asm("{ .reg .u64 t; cvta.to.shared.u64 t, %1; cvt.u32.u64 %0, t; }"
        : "=r"(a) : "l"(p));
    return a;
}
__device__ __forceinline__ void split1(float x, __nv_bfloat16& h, __nv_bfloat16& l) {
    h = __float2bfloat16(x);
    l = __float2bfloat16(x - __bfloat162float(h));
}
__device__ __forceinline__ uint32_t redux_max_u32(uint32_t v) {
    uint32_t r;
    asm volatile("redux.sync.max.u32 %0, %1, 0xffffffff;" : "=r"(r) : "r"(v));
    return r;
}
// monotonic float->uint map (order-preserving)
__device__ __forceinline__ uint32_t f2u(float x) {
    uint32_t u = __float_as_uint(x);
    return u ^ (uint32_t)(((int32_t)u >> 31) | 0x80000000);
}
__device__ __forceinline__ float u2f(uint32_t u) {
    uint32_t x = (u >> 31) ? (u ^ 0x80000000u) : ~u;
    return __uint_as_float(x);
}
__device__ __forceinline__ void csw(uint32_t& a, uint32_t& b) {  // desc compare-swap
    uint32_t hi = max(a, b), lo = min(a, b);
    a = hi; b = lo;
}

// ---------- bf16 split pre-conversion kernels ----------
__global__ void __launch_bounds__(256) conv_h(const float* __restrict__ src) {
    size_t i = ((size_t)blockIdx.x * 256 + threadIdx.x) * 4;
    float4 f = *(const float4*)(src + i);
    __nv_bfloat16 h0,l0,h1,l1,h2,l2,h3,l3;
    split1(f.x,h0,l0); split1(f.y,h1,l1); split1(f.z,h2,l2); split1(f.w,h3,l3);
    ushort4 H = { __bfloat16_as_ushort(h0), __bfloat16_as_ushort(h1),
                  __bfloat16_as_ushort(h2), __bfloat16_as_ushort(h3) };
    ushort4 L = { __bfloat16_as_ushort(l0), __bfloat16_as_ushort(l1),
                  __bfloat16_as_ushort(l2), __bfloat16_as_ushort(l3) };
    *(ushort4*)(g_Hhi + i) = H;
    *(ushort4*)(g_Hlo + i) = L;
}

__global__ void __launch_bounds__(256) conv_w(const float* __restrict__ q,
                                              const float* __restrict__ k,
                                              const float* __restrict__ v,
                                              const float* __restrict__ o) {
    size_t i4 = (size_t)blockIdx.x * 256 + threadIdx.x;
    int w = (int)(i4 >> 16);
    const float* s = (w == 0) ? q : (w == 1) ? k : (w == 2) ? v : o;
    size_t loc = (i4 & 65535) * 4;
    size_t i = i4 * 4;
    float4 f = *(const float4*)(s + loc);
    __nv_bfloat16 h0,l0,h1,l1,h2,l2,h3,l3;
    split1(f.x,h0,l0); split1(f.y,h1,l1); split1(f.z,h2,l2); split1(f.w,h3,l3);
    ushort4 H = { __bfloat16_as_ushort(h0), __bfloat16_as_ushort(h1),
                  __bfloat16_as_ushort(h2), __bfloat16_as_ushort(h3) };
    ushort4 L = { __bfloat16_as_ushort(l0), __bfloat16_as_ushort(l1),
                  __bfloat16_as_ushort(l2), __bfloat16_as_ushort(l3) };
    *(ushort4*)(g_Whi + i) = H;
    *(ushort4*)(g_Wlo + i) = L;
}

// ---------- tensor-core GEMM (mma.sync bf16 hi/lo split) ----------
#define STAGE_B   32768
#define GEMM_SMEM (3*STAGE_B)   // 3-stage ring, 96KB

__device__ __forceinline__ uint32_t swz(uint32_t off) {     // 64B rows
    return off ^ (((off >> 6) & 7) << 4);
}
__device__ __forceinline__ uint32_t swz128(uint32_t off) {  // 128B rows
    return off ^ (((off >> 7) & 7) << 4);
}

#define CPA16(dst, src) \
    asm volatile("cp.async.cg.shared.global [%0], [%1], 16;" :: "r"(dst), "l"(src))
#define CPCOMMIT() asm volatile("cp.async.commit_group;" ::: "memory")
#define CPWAIT(n)  asm volatile("cp.async.wait_group %0;" :: "n"(n) : "memory")

#define LDSM4(r, a) \
    asm volatile("ldmatrix.sync.aligned.m8n8.x4.shared.b16 {%0,%1,%2,%3}, [%4];" \
        : "=r"((r)[0]),"=r"((r)[1]),"=r"((r)[2]),"=r"((r)[3]) : "r"(a))

#define MMA16816(d, a, b0, b1) \
    asm volatile("mma.sync.aligned.m16n8k16.row.col.f32.bf16.bf16.f32 " \
        "{%0,%1,%2,%3},{%4,%5,%6,%7},{%8,%9},{%0,%1,%2,%3};" \
        : "+f"((d)[0]),"+f"((d)[1]),"+f"((d)[2]),"+f"((d)[3]) \
        : "r"((a)[0]),"r"((a)[1]),"r"((a)[2]),"r"((a)[3]), "r"(b0),"r"(b1))

// MODE 0: qkv (A=g_Hhi/lo, W = weight bx>>2). Q/K use 3 products; V uses 2.
// MODE 1: out-proj (A=g_Mhi only, W = Wo, 2 products, + residual)
template <int MODE>
__global__ void __launch_bounds__(256, 2) gemm_mma(
    const float* __restrict__ hres, float* __restrict__ outp)
{
    extern __shared__ char sm[];
    uint32_t sb = smem_u32(sm);
    int tid = threadIdx.x, lane = tid & 31, wid = tid >> 5;
    int bx = blockIdx.x;
    int m0 = blockIdx.y * 128;
    int wsel, n0;
    if (MODE == 0) { wsel = bx >> 2; n0 = (bx & 3) * 128; }
    else           { wsel = 3;       n0 = bx * 128; }

    const bool useAlo = (MODE == 0) && (wsel != 2);   // CTA-uniform

    const __nv_bfloat16* Ahi = (MODE == 0) ? g_Hhi : g_Mhi;
    const __nv_bfloat16* Alo = (MODE == 0) ? g_Hlo : g_Mhi;  // MODE1: unused
    const __nv_bfloat16* Bhi = g_Whi + (size_t)wsel * DM * DM;
    const __nv_bfloat16* Blo = g_Wlo + (size_t)wsel * DM * DM;

    // 4-tile load (Ahi, Alo, Bhi, Blo) or 3-tile (skip Alo) when unused
    auto loadc = [&](int c) {
        uint32_t stb = sb + (uint32_t)(c % 3) * STAGE_B;
        if (useAlo) {
#pragma unroll
            for (int i = 0; i < 8; i++) {
                int g = tid + i * 256;
                int tile = g >> 9;
                int idx = g & 511;
                int row = idx >> 2, kg = idx & 3;
                const __nv_bfloat16* src;
                if (tile == 0)      src = Ahi + (size_t)(m0 + row) * 512;
                else if (tile == 1) src = Alo + (size_t)(m0 + row) * 512;
                else if (tile == 2) src = Bhi + (size_t)(n0 + row) * 512;
                else                src = Blo + (size_t)(n0 + row) * 512;
                src += c * 32 + kg * 8;
                uint32_t dst = stb + tile * 8192 + swz((uint32_t)(row * 64 + kg * 16));
                CPA16(dst, src);
            }
        } else {
#pragma unroll
            for (int i = 0; i < 6; i++) {
                int g = tid + i * 256;              // 0..1535
                int tile = g >> 9;                  // 0:Ahi 1:Bhi 2:Blo
                int idx = g & 511;
                int row = idx >> 2, kg = idx & 3;
                const __nv_bfloat16* src;
                int slot;
                if (tile == 0)      { src = Ahi + (size_t)(m0 + row) * 512; slot = 0; }
                else if (tile == 1) { src = Bhi + (size_t)(n0 + row) * 512; slot = 2; }
                else                { src = Blo + (size_t)(n0 + row) * 512; slot = 3; }
                src += c * 32 + kg * 8;
                uint32_t dst = stb + slot * 8192 + swz((uint32_t)(row * 64 + kg * 16));
                CPA16(dst, src);
            }
        }
        CPCOMMIT();
    };

    int wm = wid & 3, wn = wid >> 2;      // warp tile: 32(M) x 64(N)
    float acc[64];
#pragma unroll
    for (int i = 0; i < 64; i++) acc[i] = 0.f;

    loadc(0);
    loadc(1);
    for (int c = 0; c < 16; c++) {
        if (c == 15) { CPWAIT(0); } else { CPWAIT(1); }
        __syncthreads();                  // chunk c ready; slot (c+2)%3 free
        if (c + 2 < 16) loadc(c + 2);
        uint32_t stb = sb + (uint32_t)(c % 3) * STAGE_B;
#pragma unroll
        for (int ks = 0; ks < 2; ks++) {
            uint32_t ah[2][4];
            uint32_t al[2][4] = {{0,0,0,0},{0,0,0,0}};
#pragma unroll
            for (int mt = 0; mt < 2; mt++) {
                int r = wm * 32 + mt * 16 + (lane & 15);
                uint32_t off = swz((uint32_t)(r * 64 + (ks * 16 + (lane >> 4) * 8) * 2));
                LDSM4(ah[mt], stb + off);
                if (useAlo) LDSM4(al[mt], stb + 8192 + off);
            }
#pragma unroll
            for (int p = 0; p < 4; p++) {
                int rr = wn * 64 + (2 * p + (lane >> 4)) * 8 + (lane & 7);
                uint32_t off = swz((uint32_t)(rr * 64 + (ks * 16 + ((lane >> 3) & 1) * 8) * 2));
                uint32_t bh[4], bl[4];
                LDSM4(bh, stb + 16384 + off);
                LDSM4(bl, stb + 24576 + off);
#pragma unroll
                for (int pr = 0; pr < 3; pr++) {
                    if (pr == 2 && !useAlo) continue;   // V / out-proj: 2 products
#pragma unroll
                    for (int mt = 0; mt < 2; mt++) {
#pragma unroll
                        for (int q = 0; q < 2; q++) {
                            float* d = acc + mt * 32 + (2 * p + q) * 4;
                            const uint32_t* a = (pr == 2) ? al[mt] : ah[mt];
                            const uint32_t* b = (pr == 1) ? bl : bh;
                            MMA16816(d, a, b[2 * q], b[2 * q + 1]);
                        }
                    }
                }
            }
        }
    }

    // ---- epilogue ----
#pragma unroll
    for (int mt = 0; mt < 2; mt++) {
#pragma unroll
        for (int half = 0; half < 2; half++) {
            int m = m0 + wm * 32 + mt * 16 + half * 8 + (lane >> 2);
            if (MODE == 0) {
                int b = m >> 13, v = (m >> 6) & 127, t = m & 63;
                int head = (n0 >> 6) + wn;
                size_t rb = (((size_t)(b * 64 + t) * 8 + head) * 128 + v) * 64
                            + (lane & 3) * 2;
#pragma unroll
                for (int nt = 0; nt < 8; nt++) {
                    int base = mt * 32 + nt * 4 + half * 2;
                    float2 val = make_float2(acc[base], acc[base + 1]);
                    size_t g = rb + nt * 8;
                    if (wsel == 2) {
                        ushort2 V2 = { __bfloat16_as_ushort(__float2bfloat16(val.x)),
                                       __bfloat16_as_ushort(__float2bfloat16(val.y)) };
                        *(ushort2*)(g_Vb + g) = V2;
                    } else {
                        if (wsel == 0) { val.x *= 0.125f; val.y *= 0.125f; }
                        __nv_bfloat16 h0, l0, h1, l1;
                        split1(val.x, h0, l0);
                        split1(val.y, h1, l1);
                        ushort2 H = { __bfloat16_as_ushort(h0), __bfloat16_as_ushort(h1) };
                        ushort2 L = { __bfloat16_as_ushort(l0), __bfloat16_as_ushort(l1) };
                        if (wsel == 0) {
                            *(ushort2*)(g_Qhi + g) = H;
                            *(ushort2*)(g_Qlo + g) = L;
                        } else {
                            *(ushort2*)(g_Khi + g) = H;
                            *(ushort2*)(g_Klo + g) = L;
                        }
                    }
                }
            } else {
                int Bi = m >> 7, v = m & 127;
                int b = Bi >> 6, t = Bi & 63;
                size_t dbase = (((size_t)b * 128 + v) * 64 + t) * 512
                               + n0 + wn * 64 + (lane & 3) * 2;
#pragma unroll
                for (int nt = 0; nt < 8; nt++) {
                    int base = mt * 32 + nt * 4 + half * 2;
                    float2 val = make_float2(acc[base], acc[base + 1]);
                    size_t d = dbase + nt * 8;
                    float2 hv = *(const float2*)&hres[d];
                    val.x += hv.x; val.y += hv.y;
                    *(float2*)&outp[d] = val;
                }
            }
        }
    }
}

// =====================================================================
// Attention v6: 64 q-rows per CTA (grid 16384), bf16 V, 72KB smem,
// 3 CTA/SM. tensor-core scores + sorted-tournament top-16 + sparse AV.
// =====================================================================
#define AOFF_QHI 0                // [64][128B]  8KB
#define AOFF_QLO 8192             // 8KB
#define AOFF_KHI 16384            // [128][128B] 16KB
#define AOFF_KLO 32768            // 16KB  (Q/K end 49152)
#define AOFF_S   0                // overlays Q/KHI: fp32 [64][128] = 32KB
#define AOFF_V   49152            // bf16 [128][64] = 16KB
#define AOFF_PIDX 65536           // int  [64][16] = 4KB
#define AOFF_PVAL 69632           // f32  [64][16] = 4KB
#define ATT_SMEM 73728

// XOR bank-swizzled S index ([64][128] fp32)
__device__ __forceinline__ int sidx(int r, int c) {
    return r * 128 + (c ^ ((r & 7) << 2));
}

__device__ __forceinline__ void store_h(size_t idx, float2 v) {
    ushort2 H = { __bfloat16_as_ushort(__float2bfloat16(v.x)),
                  __bfloat16_as_ushort(__float2bfloat16(v.y)) };
    *(ushort2*)(g_Mhi + idx) = H;
}

__global__ void __launch_bounds__(256, 3) attn2() {
    extern __shared__ char sm[];
    uint32_t sb = smem_u32(sm);
    float* sS = (float*)(sm + AOFF_S);
    int*   sPidx = (int*)(sm + AOFF_PIDX);
    float* sPval = (float*)(sm + AOFF_PVAL);

    int tid = threadIdx.x, lane = tid & 31, wid = tid >> 5;
    int bx = blockIdx.x;                 // ((B*8+head)<<1) | half
    int bh = bx >> 1;
    int qr0 = (bx & 1) * 64;             // q-row offset within the 128
    size_t base = (size_t)bh * 8192;     // 128*64

    // zero compacted-P arrays
    for (int i = tid; i < 1024; i += 256) { sPidx[i] = 0; sPval[i] = 0.f; }

    // ---- async loads: Q half (64 rows), K full, V bf16 ----
#pragma unroll
    for (int i = 0; i < 2; i++) {
        int g = tid + i * 256;           // 0..511 (64 rows x 8 chunks)
        int row = g >> 3, kg = g & 7;
        uint32_t doff = swz128((uint32_t)(row * 128 + kg * 16));
        CPA16(sb + AOFF_QHI + doff, g_Qhi + base + (size_t)(qr0 + row) * 64 + kg * 8);
        CPA16(sb + AOFF_QLO + doff, g_Qlo + base + (size_t)(qr0 + row) * 64 + kg * 8);
    }
#pragma unroll
    for (int i = 0; i < 4; i++) {
        int g = tid + i * 256;           // 0..1023 (128 rows x 8 chunks)
        int row = g >> 3, kg = g & 7;
        uint32_t doff = swz128((uint32_t)(row * 128 + kg * 16));
        CPA16(sb + AOFF_KHI + doff, g_Khi + base + (size_t)row * 64 + kg * 8);
        CPA16(sb + AOFF_KLO + doff, g_Klo + base + (size_t)row * 64 + kg * 8);
    }
#pragma unroll
    for (int i = 0; i < 4; i++) {
        int g = tid + i * 256;           // 0..1023 chunks of 16B (16KB)
        CPA16(sb + AOFF_V + g * 16, g_Vb + base + g * 8);
    }
    CPCOMMIT();
    CPWAIT(0);
    __syncthreads();

    // ---- S = Q @ K^T via mma (3-product split). warp tile 32(M) x 32(N) ----
    {
        int wm = wid & 1, wn = wid >> 1;
        float acc[32];
#pragma unroll
        for (int i = 0; i < 32; i++) acc[i] = 0.f;
#pragma unroll
        for (int kt = 0; kt < 4; kt++) {
            uint32_t ah[2][4], al[2][4];
#pragma unroll
            for (int mt = 0; mt < 2; mt++) {
                int r = wm * 32 + mt * 16 + (lane & 15);
                uint32_t off = swz128((uint32_t)(r * 128 + (kt * 16 + (lane >> 4) * 8) * 2));
                LDSM4(ah[mt], sb + AOFF_QHI + off);
                LDSM4(al[mt], sb + AOFF_QLO + off);
            }
#pragma unroll
            for (int p = 0; p < 2; p++) {
                int rr = wn * 32 + (2 * p + (lane >> 4)) * 8 + (lane & 7);
                uint32_t off = swz128((uint32_t)(rr * 128 + (kt * 16 + ((lane >> 3) & 1) * 8) * 2));
                uint32_t bh4[4], bl4[4];
                LDSM4(bh4, sb + AOFF_KHI + off);
                LDSM4(bl4, sb + AOFF_KLO + off);
#pragma unroll
                for (int pr = 0; pr < 3; pr++) {
#pragma unroll
                    for (int mt = 0; mt < 2; mt++) {
#pragma unroll
                        for (int q = 0; q < 2; q++) {
                            float* d = acc + mt * 16 + (2 * p + q) * 4;
                            const uint32_t* a = (pr == 2) ? al[mt] : ah[mt];
                            const uint32_t* b = (pr == 1) ? bl4 : bh4;
                            MMA16816(d, a, b[2 * q], b[2 * q + 1]);
                        }
                    }
                }
            }
        }
        __syncthreads();   // all warps done reading Q/K before S overwrites them
        // store S to overlaid SMEM [64][128] with XOR swizzle
#pragma unroll
        for (int mt = 0; mt < 2; mt++) {
#pragma unroll
            for (int half = 0; half < 2; half++) {
                int r = wm * 32 + mt * 16 + half * 8 + (lane >> 2);
#pragma unroll
                for (int nt = 0; nt < 4; nt++) {
                    int col = wn * 32 + nt * 8 + (lane & 3) * 2;
                    int bi = mt * 16 + nt * 4 + half * 2;
                    *(float2*)&sS[sidx(r, col)] = make_float2(acc[bi], acc[bi + 1]);
                }
            }
        }
    }
    __syncthreads();

    // ---- top-16 (sorted tournament) + softmax, warp per 2 rows ----
    for (int i = 0; i < 4; i++) {
        int r0 = wid * 8 + 2 * i;
        int r1 = r0 + 1;
        float4 f0 = *(float4*)&sS[sidx(r0, lane * 4)];
        float4 f1 = *(float4*)&sS[sidx(r1, lane * 4)];
        float fa0[4] = { f0.x, f0.y, f0.z, f0.w };
        float fa1[4] = { f1.x, f1.y, f1.z, f1.w };
        uint32_t uo0[4], uo1[4], u0[4], u1[4];
#pragma unroll
        for (int e = 0; e < 4; e++) {
            uo0[e] = u0[e] = f2u(fa0[e]);
            uo1[e] = u1[e] = f2u(fa1[e]);
        }
        // per-lane descending sort of 4 values (sorting network)
        csw(u0[0], u0[2]); csw(u0[1], u0[3]);
        csw(u0[0], u0[1]); csw(u0[2], u0[3]); csw(u0[1], u0[2]);
        csw(u1[0], u1[2]); csw(u1[1], u1[3]);
        csw(u1[0], u1[1]); csw(u1[2], u1[3]); csw(u1[1], u1[2]);

        float rm0 = 0.f, rm1 = 0.f;
        uint32_t th0 = 0, th1 = 0;
#pragma unroll 1
        for (int it = 0; it < TOPKN; it++) {
            uint32_t g0 = redux_max_u32(u0[0]);
            uint32_t g1 = redux_max_u32(u1[0]);
            if (it == 0) { rm0 = u2f(g0); rm1 = u2f(g1); }
            th0 = g0; th1 = g1;
            bool t0 = (u0[0] == g0);
            bool t1 = (u1[0] == g1);
            u0[0] = t0 ? u0[1] : u0[0];
            u0[1] = t0 ? u0[2] : u0[1];
            u0[2] = t0 ? u0[3] : u0[2];
            u0[3] = t0 ? 0u    : u0[3];
            u1[0] = t1 ? u1[1] : u1[0];
            u1[1] = t1 ? u1[2] : u1[1];
            u1[2] = t1 ? u1[3] : u1[2];
            u1[3] = t1 ? 0u    : u1[3];
        }
        float p0[4], p1[4];
        float s0 = 0.f, s1 = 0.f;
#pragma unroll
        for (int e = 0; e < 4; e++) {
            p0[e] = (uo0[e] >= th0) ? __expf(fa0[e] - rm0) : 0.f;
            p1[e] = (uo1[e] >= th1) ? __expf(fa1[e] - rm1) : 0.f;
            s0 += p0[e]; s1 += p1[e];
        }
#pragma unroll
        for (int o = 16; o; o >>= 1) {
            s0 += __shfl_xor_sync(FULLMASK, s0, o);
            s1 += __shfl_xor_sync(FULLMASK, s1, o);
        }
        float inv0 = 1.0f / s0, inv1 = 1.0f / s1;
        // compact (idx, p) into 16-entry lists
        int bc0 = 0, bc1 = 0;
#pragma unroll
        for (int e = 0; e < 4; e++) {
            uint32_t b0 = __ballot_sync(FULLMASK, p0[e] > 0.f);
            uint32_t b1 = __ballot_sync(FULLMASK, p1[e] > 0.f);
            uint32_t lt = (1u << lane) - 1u;
            if (p0[e] > 0.f) {
                int pos = bc0 + __popc(b0 & lt);
                if (pos < 16) { sPidx[r0 * 16 + pos] = lane * 4 + e;
                                sPval[r0 * 16 + pos] = p0[e] * inv0; }
            }
            if (p1[e] > 0.f) {
                int pos = bc1 + __popc(b1 & lt);
                if (pos < 16) { sPidx[r1 * 16 + pos] = lane * 4 + e;
                                sPval[r1 * 16 + pos] = p1[e] * inv1; }
            }
            bc0 += __popc(b0);
            bc1 += __popc(b1);
        }
    }
    __syncthreads();

    // ---- sparse AV over bf16 V: mixed[r] = sum_j p_j * V[idx_j] ----
    int B = bh >> 3, hh = bh & 7;
    const uint32_t* sVb = (const uint32_t*)(sm + AOFF_V);   // bf16x2 units
    for (int i = 0; i < 4; i++) {
        int r0 = wid * 8 + 2 * i;
        int r1 = r0 + 1;
        unsigned long long a0 = 0, a1 = 0;
#pragma unroll
        for (int j = 0; j < 16; j++) {
            int i0 = sPidx[r0 * 16 + j];
            int i1 = sPidx[r1 * 16 + j];
            float q0 = sPval[r0 * 16 + j];
            float q1 = sPval[r1 * 16 + j];
            uint32_t v0 = sVb[i0 * 32 + lane];   // bf16x2 (cols lane*2, +1)
            uint32_t v1 = sVb[i1 * 32 + lane];
            unsigned long long vv0 = pack2(__uint_as_float(v0 << 16),
                                           __uint_as_float(v0 & 0xffff0000u));
            unsigned long long vv1 = pack2(__uint_as_float(v1 << 16),
                                           __uint_as_float(v1 & 0xffff0000u));
            a0 = fma2(pack2(q0, q0), vv0, a0);
            a1 = fma2(pack2(q1, q1), vv1, a1);
        }
        size_t o0 = ((size_t)B * 128 + qr0 + r0) * 512 + hh * 64 + lane * 2;
        store_h(o0, unpack2(a0));
        store_h(o0 + 512, unpack2(a1));
    }
}

// =====================================================================
extern "C" void kernel_launch(void* const* d_in, const int* in_sizes, int n_in,
                              void* d_out, int out_size) {
    const float* h  = (const float*)d_in[0];
    const float* Wq = (const float*)d_in[1];
    const float* Wk = (const float*)d_in[2];
    const float* Wv = (const float*)d_in[3];
    const float* Wo = (const float*)d_in[4];
    float* out = (float*)d_out;

    cudaFuncSetAttribute(gemm_mma<0>, cudaFuncAttributeMaxDynamicSharedMemorySize, GEMM_SMEM);
    cudaFuncSetAttribute(gemm_mma<1>, cudaFuncAttributeMaxDynamicSharedMemorySize, GEMM_SMEM);
    cudaFuncSetAttribute(attn2, cudaFuncAttributeMaxDynamicSharedMemorySize, ATT_SMEM);

    conv_h<<<65536, 256>>>(h);
    conv_w<<<1024, 256>>>(Wq, Wk, Wv, Wo);
    gemm_mma<0><<<dim3(12, 1024), 256, GEMM_SMEM>>>(nullptr, nullptr);
    attn2<<<16384, 256, ATT_SMEM>>>();
    gemm_mma<1><<<dim3(4, 1024), 256, GEMM_SMEM>>>(h, out);
}